// round 9
// baseline (speedup 1.0000x reference)
#include <cuda_runtime.h>
#include <cuda_bf16.h>
#include <cstdint>

#define BB 2
#define SS 2048
#define EE 1024
#define HH 16
#define DD 64
#define QKPLANE (BB * HH * SS * DD)
#define SPLANE ((size_t)SS * SS)

__device__ float g_qkv[3 * QKPLANE];                       // only V plane used fp32
__device__ __nv_bfloat16 g_p_hi[(size_t)BB * HH * SS * SS];  // e = exp(S/32) hi
__device__ __nv_bfloat16 g_p_lo[(size_t)BB * HH * SS * SS];  // e lo
__device__ float g_r[(size_t)BB * SS * SS];                // 1 / sum_h e

__device__ __nv_bfloat16 g_a_hi[4096 * 1024];              // x split, later ctx split
__device__ __nv_bfloat16 g_a_lo[4096 * 1024];
__device__ __nv_bfloat16 g_wq_hi[3072 * 1024];
__device__ __nv_bfloat16 g_wq_lo[3072 * 1024];
__device__ __nv_bfloat16 g_wo_hi[1024 * 1024];
__device__ __nv_bfloat16 g_wo_lo[1024 * 1024];
__device__ __nv_bfloat16 g_q_hi[QKPLANE], g_q_lo[QKPLANE];
__device__ __nv_bfloat16 g_k_hi[QKPLANE], g_k_lo[QKPLANE];
__device__ __nv_bfloat16 g_vt_hi[QKPLANE], g_vt_lo[QKPLANE];  // [b][h][d][k]

// ===========================================================================
// helpers
// ===========================================================================
__device__ __forceinline__ uint32_t smem_u32(const void* p) {
    uint32_t a;
    asm("{ .reg .u64 t; cvta.to.shared.u64 t, %1; cvt.u32.u64 %0, t; }"
        : "=r"(a) : "l"(p));
    return a;
}
__device__ __forceinline__ void cp_async16(uint32_t saddr, const void* g) {
    asm volatile("cp.async.cg.shared.global [%0], [%1], 16;\n" :: "r"(saddr), "l"(g));
}
__device__ __forceinline__ void cp_commit() {
    asm volatile("cp.async.commit_group;\n" ::: "memory");
}
__device__ __forceinline__ void ldsm4(uint32_t& r0, uint32_t& r1, uint32_t& r2,
                                      uint32_t& r3, uint32_t a) {
    asm volatile("ldmatrix.sync.aligned.m8n8.x4.shared.b16 {%0,%1,%2,%3}, [%4];"
                 : "=r"(r0), "=r"(r1), "=r"(r2), "=r"(r3) : "r"(a));
}
__device__ __forceinline__ void mma_bf16(float* c, const uint32_t* a, uint32_t b0,
                                         uint32_t b1) {
    asm volatile(
        "mma.sync.aligned.m16n8k16.row.col.f32.bf16.bf16.f32 "
        "{%0,%1,%2,%3},{%4,%5,%6,%7},{%8,%9},{%0,%1,%2,%3};"
        : "+f"(c[0]), "+f"(c[1]), "+f"(c[2]), "+f"(c[3])
        : "r"(a[0]), "r"(a[1]), "r"(a[2]), "r"(a[3]), "r"(b0), "r"(b1));
}
__device__ __forceinline__ void split4(float4 v, uint32_t& h01, uint32_t& h23,
                                       uint32_t& l01, uint32_t& l23) {
    asm("cvt.rn.bf16x2.f32 %0, %1, %2;" : "=r"(h01) : "f"(v.y), "f"(v.x));
    asm("cvt.rn.bf16x2.f32 %0, %1, %2;" : "=r"(h23) : "f"(v.w), "f"(v.z));
    float q0 = v.x - __uint_as_float(h01 << 16);
    float q1 = v.y - __uint_as_float(h01 & 0xffff0000u);
    float q2 = v.z - __uint_as_float(h23 << 16);
    float q3 = v.w - __uint_as_float(h23 & 0xffff0000u);
    asm("cvt.rn.bf16x2.f32 %0, %1, %2;" : "=r"(l01) : "f"(q1), "f"(q0));
    asm("cvt.rn.bf16x2.f32 %0, %1, %2;" : "=r"(l23) : "f"(q3), "f"(q2));
}
__device__ __forceinline__ void split2(float a, float b, uint32_t& hi, uint32_t& lo) {
    asm("cvt.rn.bf16x2.f32 %0, %1, %2;" : "=r"(hi) : "f"(b), "f"(a));
    float ra = a - __uint_as_float(hi << 16);
    float rb = b - __uint_as_float(hi & 0xffff0000u);
    asm("cvt.rn.bf16x2.f32 %0, %1, %2;" : "=r"(lo) : "f"(rb), "f"(ra));
}

// ===========================================================================
// generic fp32 -> bf16 hi/lo split
// ===========================================================================
__global__ __launch_bounds__(256) void cvt_split_p(const float4* __restrict__ src,
                                                   uint2* __restrict__ hp,
                                                   uint2* __restrict__ lp) {
    int i = blockIdx.x * 256 + threadIdx.x;
    float4 v = src[i];
    uint32_t h01, h23, l01, l23;
    split4(v, h01, h23, l01, l23);
    hp[i] = make_uint2(h01, h23);
    lp[i] = make_uint2(l01, l23);
}

// ===========================================================================
// V transpose + split: g_qkv V plane [b][h][k][d] -> g_vt [b][h][d][k] bf16
// ===========================================================================
__global__ __launch_bounds__(256) void vt_split() {
    int idx = blockIdx.x * 256 + threadIdx.x;
    int k4 = idx & 511;
    int d = (idx >> 9) & 63;
    int bh = idx >> 15;
    const float* vp = g_qkv + 2 * QKPLANE + ((size_t)bh * SS + k4 * 4) * DD + d;
    float4 v = make_float4(vp[0], vp[64], vp[128], vp[192]);
    uint32_t h01, h23, l01, l23;
    split4(v, h01, h23, l01, l23);
    size_t o = ((size_t)bh * DD + d) * 512 + k4;
    ((uint2*)g_vt_hi)[o] = make_uint2(h01, h23);
    ((uint2*)g_vt_lo)[o] = make_uint2(l01, l23);
}

// ===========================================================================
// denominator: r[b,q,k] = 1 / sum_h (e_hi + e_lo)
// ===========================================================================
__global__ __launch_bounds__(256) void denom_r() {
    int idx = blockIdx.x * 256 + threadIdx.x;   // 2*2048*512
    int k4 = idx & 511;
    int q = (idx >> 9) & 2047;
    int b = idx >> 20;
    const uint2* phi = (const uint2*)g_p_hi;
    const uint2* plo = (const uint2*)g_p_lo;
    size_t base = ((size_t)b * HH * SPLANE + (size_t)q * SS + k4 * 4) >> 2;
    size_t hstep = SPLANE >> 2;
    float4 s = make_float4(0.f, 0.f, 0.f, 0.f);
#pragma unroll
    for (int h = 0; h < 16; h++) {
        uint2 uh = phi[base + h * hstep];
        uint2 ul = plo[base + h * hstep];
        s.x += __uint_as_float(uh.x << 16) + __uint_as_float(ul.x << 16);
        s.y += __uint_as_float(uh.x & 0xffff0000u) + __uint_as_float(ul.x & 0xffff0000u);
        s.z += __uint_as_float(uh.y << 16) + __uint_as_float(ul.y << 16);
        s.w += __uint_as_float(uh.y & 0xffff0000u) + __uint_as_float(ul.y & 0xffff0000u);
    }
    float4 r;
    r.x = __fdividef(1.f, s.x);
    r.y = __fdividef(1.f, s.y);
    r.z = __fdividef(1.f, s.z);
    r.w = __fdividef(1.f, s.w);
    ((float4*)g_r)[((size_t)b * SS + q) * 512 + k4] = r;
}

// ===========================================================================
// HMMA bf16-split NT GEMM.
// MODE 0: out-proj (A=g_a(ctx splits), bias, row-major fp32 out N=1024)
// MODE 1: QKV (bias; Q,K -> bf16 splits; V -> fp32 g_qkv)
// MODE 2: scores (z=(b,h), K=64; epilogue: exp -> e hi/lo bf16)
// ===========================================================================
template <int MODE, int NT, int K>
__global__ __launch_bounds__(256, 2) void tgemm(
    const __nv_bfloat16* __restrict__ Ah0, const __nv_bfloat16* __restrict__ Al0,
    const __nv_bfloat16* __restrict__ Wh0, const __nv_bfloat16* __restrict__ Wl0,
    const float* __restrict__ bias, float* __restrict__ Cout,
    int strideA, int strideW) {
    extern __shared__ char dsm[];
    uint32_t sbase = smem_u32(dsm);
    constexpr int TILE_A = 10240;
    constexpr int TILE_W = NT * 80;
    constexpr int BUF = 2 * TILE_A + 2 * TILE_W;
    constexpr int NP = NT / 32;

    int z = blockIdx.z;
    const __nv_bfloat16* Ah = Ah0 + (size_t)z * strideA;
    const __nv_bfloat16* Al = Al0 + (size_t)z * strideA;
    const __nv_bfloat16* Wh = Wh0 + (size_t)z * strideW;
    const __nv_bfloat16* Wl = Wl0 + (size_t)z * strideW;

    int tid = threadIdx.x, lane = tid & 31, wid = tid >> 5;
    int wm = wid & 3, wn = wid >> 2;
    int m0 = blockIdx.y * 128, n0 = blockIdx.x * NT;

    float acc[2][2 * NP][4];
#pragma unroll
    for (int i = 0; i < 2; i++)
#pragma unroll
        for (int j = 0; j < 2 * NP; j++)
#pragma unroll
            for (int q = 0; q < 4; q++) acc[i][j][q] = 0.f;

    const int NC = K / 32;
    const int lrow = tid >> 2;
    const int seg = tid & 3;

    auto issue = [&](int c) {
        uint32_t sb = sbase + (c & 1) * BUF;
        int gcol = c * 32 + seg * 8;
#pragma unroll
        for (int rr = 0; rr < 2; rr++) {
            int row = lrow + rr * 64;
            uint32_t soff = (uint32_t)(row * 80 + seg * 16);
            cp_async16(sb + soff, Ah + (size_t)(m0 + row) * K + gcol);
            cp_async16(sb + TILE_A + soff, Al + (size_t)(m0 + row) * K + gcol);
        }
#pragma unroll
        for (int rr = 0; rr < NT / 64; rr++) {
            int row = lrow + rr * 64;
            uint32_t soff = (uint32_t)(row * 80 + seg * 16);
            cp_async16(sb + 2 * TILE_A + soff, Wh + (size_t)(n0 + row) * K + gcol);
            cp_async16(sb + 2 * TILE_A + TILE_W + soff, Wl + (size_t)(n0 + row) * K + gcol);
        }
        cp_commit();
    };

    issue(0);

    for (int c = 0; c < NC; c++) {
        if (c + 1 < NC) {
            issue(c + 1);
            asm volatile("cp.async.wait_group 1;\n" ::: "memory");
        } else {
            asm volatile("cp.async.wait_group 0;\n" ::: "memory");
        }
        __syncthreads();

        uint32_t sb = sbase + (c & 1) * BUF;
        uint32_t a_addr = sb + (uint32_t)((wm * 32 + (lane & 15)) * 80 + (lane >> 4) * 16);
        uint32_t b_addr = sb + 2 * TILE_A +
                          (uint32_t)((wn * (NT / 2) + (lane >> 4) * 8 + (lane & 7)) * 80 +
                                     ((lane >> 3) & 1) * 16);

#pragma unroll
        for (int ks = 0; ks < 2; ks++) {
            uint32_t ah[2][4], al[2][4];
#pragma unroll
            for (int mb = 0; mb < 2; mb++) {
                uint32_t ao = a_addr + ks * 32 + mb * (16 * 80);
                ldsm4(ah[mb][0], ah[mb][1], ah[mb][2], ah[mb][3], ao);
                ldsm4(al[mb][0], al[mb][1], al[mb][2], al[mb][3], ao + TILE_A);
            }
#pragma unroll
            for (int np = 0; np < NP; np++) {
                uint32_t bo = b_addr + ks * 32 + np * (16 * 80);
                uint32_t h0, h1, h2, h3, l0, l1, l2, l3;
                ldsm4(h0, h1, h2, h3, bo);
                ldsm4(l0, l1, l2, l3, bo + TILE_W);
#pragma unroll
                for (int mb = 0; mb < 2; mb++) {
                    mma_bf16(acc[mb][2 * np],     ah[mb], h0, h1);
                    mma_bf16(acc[mb][2 * np],     al[mb], h0, h1);
                    mma_bf16(acc[mb][2 * np],     ah[mb], l0, l1);
                    mma_bf16(acc[mb][2 * np + 1], ah[mb], h2, h3);
                    mma_bf16(acc[mb][2 * np + 1], al[mb], h2, h3);
                    mma_bf16(acc[mb][2 * np + 1], ah[mb], l2, l3);
                }
            }
        }
        __syncthreads();
    }

    int lr = lane >> 2, lc = lane & 3;
#pragma unroll
    for (int mb = 0; mb < 2; mb++) {
#pragma unroll
        for (int nb = 0; nb < 2 * NP; nb++) {
            int n = n0 + wn * (NT / 2) + nb * 8 + lc * 2;
            int m_lo = m0 + wm * 32 + mb * 16 + lr;
            float* a4 = acc[mb][nb];
            if constexpr (MODE == 0) {
                float2 bv = *(const float2*)(bias + n);
                *(float2*)(Cout + (size_t)m_lo * 1024 + n) =
                    make_float2(a4[0] + bv.x, a4[1] + bv.y);
                *(float2*)(Cout + (size_t)(m_lo + 8) * 1024 + n) =
                    make_float2(a4[2] + bv.x, a4[3] + bv.y);
            } else if constexpr (MODE == 1) {
                float2 bv = *(const float2*)(bias + n);
                int which = n >> 10;
                int hh = (n & 1023) >> 6;
                int d = n & 63;
#pragma unroll
                for (int half = 0; half < 2; half++) {
                    int m = m_lo + half * 8;
                    int b_ = m >> 11;
                    int s = m & 2047;
                    float v0 = a4[2 * half] + bv.x;
                    float v1 = a4[2 * half + 1] + bv.y;
                    size_t idx = (((size_t)b_ * HH + hh) * SS + s) * DD + d;
                    if (which == 2) {
                        *(float2*)(g_qkv + 2 * QKPLANE + idx) = make_float2(v0, v1);
                    } else {
                        uint32_t hi, lo;
                        split2(v0, v1, hi, lo);
                        uint32_t* ph = which ? (uint32_t*)g_k_hi : (uint32_t*)g_q_hi;
                        uint32_t* pl = which ? (uint32_t*)g_k_lo : (uint32_t*)g_q_lo;
                        ph[idx >> 1] = hi;
                        pl[idx >> 1] = lo;
                    }
                }
            } else {
                // MODE 2: e = exp(S/32) -> bf16 hi/lo
                uint32_t* phi = (uint32_t*)g_p_hi;
                uint32_t* plo = (uint32_t*)g_p_lo;
                size_t base = (size_t)z * SPLANE;
                float e0 = __expf(a4[0] * 0.03125f);
                float e1 = __expf(a4[1] * 0.03125f);
                float e2 = __expf(a4[2] * 0.03125f);
                float e3 = __expf(a4[3] * 0.03125f);
                uint32_t hi, lo;
                split2(e0, e1, hi, lo);
                size_t i0 = (base + (size_t)m_lo * SS + n) >> 1;
                phi[i0] = hi; plo[i0] = lo;
                split2(e2, e3, hi, lo);
                size_t i1 = (base + (size_t)(m_lo + 8) * SS + n) >> 1;
                phi[i1] = hi; plo[i1] = lo;
            }
        }
    }
}

// ===========================================================================
// PV GEMM: ctx[b,h,q,d] = sum_k (e*r) V[k,d]; A built on the fly from e,r.
// NT=64, K=2048, 128x64 tile per CTA, epilogue writes ctx bf16 splits.
// ===========================================================================
#define ABUF 10240
#define WBUF 5120
#define PV_SMEM (4 * ABUF + 4 * WBUF)

__global__ __launch_bounds__(256, 2) void pv_gemm() {
    extern __shared__ char dsm[];
    uint32_t sbase = smem_u32(dsm);

    int z = blockIdx.z;
    int b = z >> 4, h = z & 15;
    const __nv_bfloat16* ehi = g_p_hi + (size_t)z * SPLANE;
    const __nv_bfloat16* elo = g_p_lo + (size_t)z * SPLANE;
    const float* rp = g_r + (size_t)b * SPLANE;
    const __nv_bfloat16* wh = g_vt_hi + (size_t)z * SS * DD;
    const __nv_bfloat16* wl = g_vt_lo + (size_t)z * SS * DD;

    int tid = threadIdx.x, lane = tid & 31, wid = tid >> 5;
    int wm = wid & 3, wn = wid >> 2;
    int m0 = blockIdx.y * 128;

    float acc[2][4][4];
#pragma unroll
    for (int i = 0; i < 2; i++)
#pragma unroll
        for (int j = 0; j < 4; j++)
#pragma unroll
            for (int q = 0; q < 4; q++) acc[i][j][q] = 0.f;

    const int NC = SS / 32;        // 64
    const int lrow = tid >> 2;     // 0..63
    const int seg = tid & 3;

    uint4 REh[2], REl[2];
    float4 RR[2][2];

    auto issueW = [&](int c) {
        uint32_t sb = sbase + 4 * ABUF + (c & 1) * 2 * WBUF;
        int gcol = c * 32 + seg * 8;
        uint32_t soff = (uint32_t)(lrow * 80 + seg * 16);
        cp_async16(sb + soff, wh + (size_t)lrow * SS + gcol);
        cp_async16(sb + WBUF + soff, wl + (size_t)lrow * SS + gcol);
        cp_commit();
    };
    auto prefetchA = [&](int c) {
#pragma unroll
        for (int rr = 0; rr < 2; rr++) {
            int row = lrow + rr * 64;
            size_t gp = (size_t)(m0 + row) * SS + c * 32 + seg * 8;
            REh[rr] = *(const uint4*)(ehi + gp);
            REl[rr] = *(const uint4*)(elo + gp);
            RR[rr][0] = *(const float4*)(rp + gp);
            RR[rr][1] = *(const float4*)(rp + gp + 4);
        }
    };
    auto stsA = [&](int c) {
        char* sb = dsm + (c & 1) * 2 * ABUF;
#pragma unroll
        for (int rr = 0; rr < 2; rr++) {
            int row = lrow + rr * 64;
            const uint32_t* uh = (const uint32_t*)&REh[rr];
            const uint32_t* ul = (const uint32_t*)&REl[rr];
            float p[8];
#pragma unroll
            for (int j = 0; j < 4; j++) {
                float e0 = __uint_as_float(uh[j] << 16) + __uint_as_float(ul[j] << 16);
                float e1 = __uint_as_float(uh[j] & 0xffff0000u) +
                           __uint_as_float(ul[j] & 0xffff0000u);
                float r0 = (j < 2) ? ((j & 1) ? RR[rr][0].z : RR[rr][0].x)
                                   : ((j & 1) ? RR[rr][1].z : RR[rr][1].x);
                float r1 = (j < 2) ? ((j & 1) ? RR[rr][0].w : RR[rr][0].y)
                                   : ((j & 1) ? RR[rr][1].w : RR[rr][1].y);
                p[j * 2] = e0 * r0;
                p[j * 2 + 1] = e1 * r1;
            }
            uint32_t h01, h23, h45, h67, l01, l23, l45, l67;
            split4(make_float4(p[0], p[1], p[2], p[3]), h01, h23, l01, l23);
            split4(make_float4(p[4], p[5], p[6], p[7]), h45, h67, l45, l67);
            uint32_t soff = (uint32_t)(row * 80 + seg * 16);
            *(uint4*)(sb + soff) = make_uint4(h01, h23, h45, h67);
            *(uint4*)(sb + ABUF + soff) = make_uint4(l01, l23, l45, l67);
        }
    };

    prefetchA(0);
    issueW(0);

    for (int c = 0; c < NC; c++) {
        stsA(c);
        if (c + 1 < NC) {
            prefetchA(c + 1);
            issueW(c + 1);
            asm volatile("cp.async.wait_group 1;\n" ::: "memory");
        } else {
            asm volatile("cp.async.wait_group 0;\n" ::: "memory");
        }
        __syncthreads();

        uint32_t sa = sbase + (c & 1) * 2 * ABUF +
                      (uint32_t)((wm * 32 + (lane & 15)) * 80 + (lane >> 4) * 16);
        uint32_t sw = sbase + 4 * ABUF + (c & 1) * 2 * WBUF +
                      (uint32_t)((wn * 32 + (lane >> 4) * 8 + (lane & 7)) * 80 +
                                 ((lane >> 3) & 1) * 16);

#pragma unroll
        for (int ks = 0; ks < 2; ks++) {
            uint32_t ah[2][4], al[2][4];
#pragma unroll
            for (int mb = 0; mb < 2; mb++) {
                uint32_t ao = sa + ks * 32 + mb * (16 * 80);
                ldsm4(ah[mb][0], ah[mb][1], ah[mb][2], ah[mb][3], ao);
                ldsm4(al[mb][0], al[mb][1], al[mb][2], al[mb][3], ao + ABUF);
            }
#pragma unroll
            for (int np = 0; np < 2; np++) {
                uint32_t bo = sw + ks * 32 + np * (16 * 80);
                uint32_t h0, h1, h2, h3, l0, l1, l2, l3;
                ldsm4(h0, h1, h2, h3, bo);
                ldsm4(l0, l1, l2, l3, bo + WBUF);
#pragma unroll
                for (int mb = 0; mb < 2; mb++) {
                    mma_bf16(acc[mb][2 * np],     ah[mb], h0, h1);
                    mma_bf16(acc[mb][2 * np],     al[mb], h0, h1);
                    mma_bf16(acc[mb][2 * np],     ah[mb], l0, l1);
                    mma_bf16(acc[mb][2 * np + 1], ah[mb], h2, h3);
                    mma_bf16(acc[mb][2 * np + 1], al[mb], h2, h3);
                    mma_bf16(acc[mb][2 * np + 1], ah[mb], l2, l3);
                }
            }
        }
        __syncthreads();
    }

    // epilogue: write ctx bf16 splits into g_a (layout [b][s][h*64+d])
    int lr = lane >> 2, lc = lane & 3;
    uint32_t* ch = (uint32_t*)g_a_hi;
    uint32_t* cl = (uint32_t*)g_a_lo;
#pragma unroll
    for (int mb = 0; mb < 2; mb++) {
#pragma unroll
        for (int nb = 0; nb < 4; nb++) {
            int n = wn * 32 + nb * 8 + lc * 2;
            int m_lo = m0 + wm * 32 + mb * 16 + lr;
            float* a4 = acc[mb][nb];
            size_t i0 = ((size_t)(b * SS + m_lo) * EE + h * DD + n) >> 1;
            size_t i1 = i0 + 4 * EE;           // +8 rows => +8*EE floats => /2
            uint32_t hi, lo;
            split2(a4[0], a4[1], hi, lo);
            ch[i0] = hi; cl[i0] = lo;
            split2(a4[2], a4[3], hi, lo);
            ch[i1] = hi; cl[i1] = lo;
        }
    }
}

// ===========================================================================
extern "C" void kernel_launch(void* const* d_in, const int* in_sizes, int n_in,
                              void* d_out, int out_size) {
    const float* x     = (const float*)d_in[0];
    const float* w_qkv = (const float*)d_in[1];
    const float* b_qkv = (const float*)d_in[2];
    const float* w_out = (const float*)d_in[3];
    const float* b_out = (const float*)d_in[4];
    float* out = (float*)d_out;

    void *p_ahi, *p_alo, *p_wqh, *p_wql, *p_woh, *p_wol, *p_qhi, *p_qlo,
         *p_khi, *p_klo;
    cudaGetSymbolAddress(&p_ahi, g_a_hi);
    cudaGetSymbolAddress(&p_alo, g_a_lo);
    cudaGetSymbolAddress(&p_wqh, g_wq_hi);
    cudaGetSymbolAddress(&p_wql, g_wq_lo);
    cudaGetSymbolAddress(&p_woh, g_wo_hi);
    cudaGetSymbolAddress(&p_wol, g_wo_lo);
    cudaGetSymbolAddress(&p_qhi, g_q_hi);
    cudaGetSymbolAddress(&p_qlo, g_q_lo);
    cudaGetSymbolAddress(&p_khi, g_k_hi);
    cudaGetSymbolAddress(&p_klo, g_k_lo);

    const int SM128 = 2 * (2 * 10240 + 2 * 10240);
    cudaFuncSetAttribute(tgemm<1, 128, 1024>, cudaFuncAttributeMaxDynamicSharedMemorySize, SM128);
    cudaFuncSetAttribute(tgemm<0, 128, 1024>, cudaFuncAttributeMaxDynamicSharedMemorySize, SM128);
    cudaFuncSetAttribute(tgemm<2, 128, 64>,   cudaFuncAttributeMaxDynamicSharedMemorySize, SM128);
    cudaFuncSetAttribute(pv_gemm, cudaFuncAttributeMaxDynamicSharedMemorySize, PV_SMEM);

    // 1) split x, w_qkv, w_out
    cvt_split_p<<<4096, 256>>>((const float4*)x, (uint2*)p_ahi, (uint2*)p_alo);
    cvt_split_p<<<3072, 256>>>((const float4*)w_qkv, (uint2*)p_wqh, (uint2*)p_wql);
    cvt_split_p<<<1024, 256>>>((const float4*)w_out, (uint2*)p_woh, (uint2*)p_wol);

    // 2) QKV projection -> Q/K bf16 splits + V fp32
    tgemm<1, 128, 1024><<<dim3(24, 32, 1), 256, SM128>>>(
        (const __nv_bfloat16*)p_ahi, (const __nv_bfloat16*)p_alo,
        (const __nv_bfloat16*)p_wqh, (const __nv_bfloat16*)p_wql,
        b_qkv, nullptr, 0, 0);

    // 3) transpose+split V
    vt_split<<<4096, 256>>>();

    // 4) scores + exp -> e hi/lo
    tgemm<2, 128, 64><<<dim3(16, 16, 32), 256, SM128>>>(
        (const __nv_bfloat16*)p_qhi, (const __nv_bfloat16*)p_qlo,
        (const __nv_bfloat16*)p_khi, (const __nv_bfloat16*)p_klo,
        nullptr, nullptr, SS * DD, SS * DD);

    // 5) denominators
    denom_r<<<8192, 256>>>();

    // 6) ctx = (e*r) V -> ctx bf16 splits in g_a
    pv_gemm<<<dim3(1, 16, 32), 256, PV_SMEM>>>();

    // 7) out-projection
    tgemm<0, 128, 1024><<<dim3(8, 32, 1), 256, SM128>>>(
        (const __nv_bfloat16*)p_ahi, (const __nv_bfloat16*)p_alo,
        (const __nv_bfloat16*)p_woh, (const __nv_bfloat16*)p_wol,
        b_out, out, 0, 0);
}

// round 10
// speedup vs baseline: 1.1654x; 1.1654x over previous
#include <cuda_runtime.h>
#include <cuda_bf16.h>
#include <cstdint>

#define BB 2
#define SS 2048
#define EE 1024
#define HH 16
#define DD 64
#define QKPLANE (BB * HH * SS * DD)
#define SPLANE ((size_t)SS * SS)

__device__ float g_qkv[3 * QKPLANE];                        // V plane fp32 (Q/K unused)
__device__ float g_S[(size_t)BB * HH * SS * SS];            // scores fp32
__device__ __nv_bfloat16 g_p_hi[(size_t)BB * HH * SS * SS]; // P splits
__device__ __nv_bfloat16 g_p_lo[(size_t)BB * HH * SS * SS];

__device__ __nv_bfloat16 g_a_hi[4096 * 1024];               // x split, later ctx split
__device__ __nv_bfloat16 g_a_lo[4096 * 1024];
__device__ __nv_bfloat16 g_wq_hi[3072 * 1024];
__device__ __nv_bfloat16 g_wq_lo[3072 * 1024];
__device__ __nv_bfloat16 g_wo_hi[1024 * 1024];
__device__ __nv_bfloat16 g_wo_lo[1024 * 1024];
__device__ __nv_bfloat16 g_q_hi[QKPLANE];                   // Q,K bf16 (rn) only
__device__ __nv_bfloat16 g_k_hi[QKPLANE];
__device__ __nv_bfloat16 g_vt_hi[QKPLANE], g_vt_lo[QKPLANE];  // [b][h][d][k]

// ===========================================================================
// helpers
// ===========================================================================
__device__ __forceinline__ uint32_t smem_u32(const void* p) {
    uint32_t a;
    asm("{ .reg .u64 t; cvta.to.shared.u64 t, %1; cvt.u32.u64 %0, t; }"
        : "=r"(a) : "l"(p));
    return a;
}
__device__ __forceinline__ void cp_async16(uint32_t saddr, const void* g) {
    asm volatile("cp.async.cg.shared.global [%0], [%1], 16;\n" :: "r"(saddr), "l"(g));
}
__device__ __forceinline__ void cp_commit() {
    asm volatile("cp.async.commit_group;\n" ::: "memory");
}
__device__ __forceinline__ void ldsm4(uint32_t& r0, uint32_t& r1, uint32_t& r2,
                                      uint32_t& r3, uint32_t a) {
    asm volatile("ldmatrix.sync.aligned.m8n8.x4.shared.b16 {%0,%1,%2,%3}, [%4];"
                 : "=r"(r0), "=r"(r1), "=r"(r2), "=r"(r3) : "r"(a));
}
__device__ __forceinline__ void mma_bf16(float* c, const uint32_t* a, uint32_t b0,
                                         uint32_t b1) {
    asm volatile(
        "mma.sync.aligned.m16n8k16.row.col.f32.bf16.bf16.f32 "
        "{%0,%1,%2,%3},{%4,%5,%6,%7},{%8,%9},{%0,%1,%2,%3};"
        : "+f"(c[0]), "+f"(c[1]), "+f"(c[2]), "+f"(c[3])
        : "r"(a[0]), "r"(a[1]), "r"(a[2]), "r"(a[3]), "r"(b0), "r"(b1));
}
__device__ __forceinline__ void split4(float4 v, uint32_t& h01, uint32_t& h23,
                                       uint32_t& l01, uint32_t& l23) {
    asm("cvt.rn.bf16x2.f32 %0, %1, %2;" : "=r"(h01) : "f"(v.y), "f"(v.x));
    asm("cvt.rn.bf16x2.f32 %0, %1, %2;" : "=r"(h23) : "f"(v.w), "f"(v.z));
    float q0 = v.x - __uint_as_float(h01 << 16);
    float q1 = v.y - __uint_as_float(h01 & 0xffff0000u);
    float q2 = v.z - __uint_as_float(h23 << 16);
    float q3 = v.w - __uint_as_float(h23 & 0xffff0000u);
    asm("cvt.rn.bf16x2.f32 %0, %1, %2;" : "=r"(l01) : "f"(q1), "f"(q0));
    asm("cvt.rn.bf16x2.f32 %0, %1, %2;" : "=r"(l23) : "f"(q3), "f"(q2));
}
__device__ __forceinline__ void split2(float a, float b, uint32_t& hi, uint32_t& lo) {
    asm("cvt.rn.bf16x2.f32 %0, %1, %2;" : "=r"(hi) : "f"(b), "f"(a));
    float ra = a - __uint_as_float(hi << 16);
    float rb = b - __uint_as_float(hi & 0xffff0000u);
    asm("cvt.rn.bf16x2.f32 %0, %1, %2;" : "=r"(lo) : "f"(rb), "f"(ra));
}

// ===========================================================================
// generic fp32 -> bf16 hi/lo split
// ===========================================================================
__global__ __launch_bounds__(256) void cvt_split_p(const float4* __restrict__ src,
                                                   uint2* __restrict__ hp,
                                                   uint2* __restrict__ lp) {
    int i = blockIdx.x * 256 + threadIdx.x;
    float4 v = src[i];
    uint32_t h01, h23, l01, l23;
    split4(v, h01, h23, l01, l23);
    hp[i] = make_uint2(h01, h23);
    lp[i] = make_uint2(l01, l23);
}

// ===========================================================================
// V transpose + split: g_qkv V plane [b][h][k][d] -> g_vt [b][h][d][k] bf16
// ===========================================================================
__global__ __launch_bounds__(256) void vt_split() {
    int idx = blockIdx.x * 256 + threadIdx.x;
    int k4 = idx & 511;
    int d = (idx >> 9) & 63;
    int bh = idx >> 15;
    const float* vp = g_qkv + 2 * QKPLANE + ((size_t)bh * SS + k4 * 4) * DD + d;
    float4 v = make_float4(vp[0], vp[64], vp[128], vp[192]);
    uint32_t h01, h23, l01, l23;
    split4(v, h01, h23, l01, l23);
    size_t o = ((size_t)bh * DD + d) * 512 + k4;
    ((uint2*)g_vt_hi)[o] = make_uint2(h01, h23);
    ((uint2*)g_vt_lo)[o] = make_uint2(l01, l23);
}

// ===========================================================================
// softmax over HEAD axis: P = exp(S/32)/sum_h exp(S/32), P -> bf16 hi/lo
// ===========================================================================
__global__ __launch_bounds__(256) void softmax_h() {
    int idx = blockIdx.x * 256 + threadIdx.x;
    int k4 = idx & 511;
    int q = (idx >> 9) & 2047;
    int b = idx >> 20;
    const size_t hs = (size_t)SS * 512;
    size_t base = ((size_t)b * HH * SS + q) * 512 + k4;

    const float4* S4 = (const float4*)g_S;
    float4 e[16];
    float4 ds = make_float4(0.f, 0.f, 0.f, 0.f);
#pragma unroll
    for (int h = 0; h < 16; h++) {
        float4 s = S4[base + (size_t)h * hs];
        e[h].x = __expf(s.x * 0.03125f);
        e[h].y = __expf(s.y * 0.03125f);
        e[h].z = __expf(s.z * 0.03125f);
        e[h].w = __expf(s.w * 0.03125f);
        ds.x += e[h].x; ds.y += e[h].y; ds.z += e[h].z; ds.w += e[h].w;
    }
    float4 r;
    r.x = __fdividef(1.f, ds.x);
    r.y = __fdividef(1.f, ds.y);
    r.z = __fdividef(1.f, ds.z);
    r.w = __fdividef(1.f, ds.w);
    uint2* phi = (uint2*)g_p_hi;
    uint2* plo = (uint2*)g_p_lo;
#pragma unroll
    for (int h = 0; h < 16; h++) {
        float4 p = make_float4(e[h].x * r.x, e[h].y * r.y, e[h].z * r.z, e[h].w * r.w);
        uint32_t h01, h23, l01, l23;
        split4(p, h01, h23, l01, l23);
        size_t o = base + (size_t)h * hs;
        phi[o] = make_uint2(h01, h23);
        plo[o] = make_uint2(l01, l23);
    }
}

// ===========================================================================
// HMMA NT GEMM; SPLITS = 3 (bf16-split, accurate) or 1 (bf16-only).
// MODE 0: out-proj (bias, fp32 out, N=1024)
// MODE 1: QKV (bias; Q,K -> rn-bf16; V -> fp32 g_qkv)
// MODE 2: scores (z=(b,h), K=64, SPLITS=1, fp32 S out)
// MODE 3: PV ctx (z=(b,h), NT=64; epilogue -> ctx bf16 hi/lo in g_a)
// ===========================================================================
template <int MODE, int NT, int K, int SPLITS>
__global__ __launch_bounds__(256, 2) void tgemm(
    const __nv_bfloat16* __restrict__ Ah0, const __nv_bfloat16* __restrict__ Al0,
    const __nv_bfloat16* __restrict__ Wh0, const __nv_bfloat16* __restrict__ Wl0,
    const float* __restrict__ bias, float* __restrict__ Cout,
    int strideA, int strideW) {
    extern __shared__ char dsm[];
    uint32_t sbase = smem_u32(dsm);
    constexpr int TILE_A = 10240;
    constexpr int TILE_W = NT * 80;
    constexpr int BUF = 2 * TILE_A + 2 * TILE_W;
    constexpr int NP = NT / 32;

    int z = blockIdx.z;
    const __nv_bfloat16* Ah = Ah0 + (size_t)z * strideA;
    const __nv_bfloat16* Al = Al0 + (size_t)z * strideA;
    const __nv_bfloat16* Wh = Wh0 + (size_t)z * strideW;
    const __nv_bfloat16* Wl = Wl0 + (size_t)z * strideW;

    int tid = threadIdx.x, lane = tid & 31, wid = tid >> 5;
    int wm = wid & 3, wn = wid >> 2;
    int m0 = blockIdx.y * 128, n0 = blockIdx.x * NT;

    float acc[2][2 * NP][4];
#pragma unroll
    for (int i = 0; i < 2; i++)
#pragma unroll
        for (int j = 0; j < 2 * NP; j++)
#pragma unroll
            for (int q = 0; q < 4; q++) acc[i][j][q] = 0.f;

    const int NC = K / 32;
    const int lrow = tid >> 2;
    const int seg = tid & 3;

    auto issue = [&](int c) {
        uint32_t sb = sbase + (c & 1) * BUF;
        int gcol = c * 32 + seg * 8;
#pragma unroll
        for (int rr = 0; rr < 2; rr++) {
            int row = lrow + rr * 64;
            uint32_t soff = (uint32_t)(row * 80 + seg * 16);
            cp_async16(sb + soff, Ah + (size_t)(m0 + row) * K + gcol);
            if (SPLITS == 3)
                cp_async16(sb + TILE_A + soff, Al + (size_t)(m0 + row) * K + gcol);
        }
#pragma unroll
        for (int rr = 0; rr < NT / 64; rr++) {
            int row = lrow + rr * 64;
            uint32_t soff = (uint32_t)(row * 80 + seg * 16);
            cp_async16(sb + 2 * TILE_A + soff, Wh + (size_t)(n0 + row) * K + gcol);
            if (SPLITS == 3)
                cp_async16(sb + 2 * TILE_A + TILE_W + soff,
                           Wl + (size_t)(n0 + row) * K + gcol);
        }
        cp_commit();
    };

    issue(0);

    for (int c = 0; c < NC; c++) {
        if (c + 1 < NC) {
            issue(c + 1);
            asm volatile("cp.async.wait_group 1;\n" ::: "memory");
        } else {
            asm volatile("cp.async.wait_group 0;\n" ::: "memory");
        }
        __syncthreads();

        uint32_t sb = sbase + (c & 1) * BUF;
        uint32_t a_addr = sb + (uint32_t)((wm * 32 + (lane & 15)) * 80 + (lane >> 4) * 16);
        uint32_t b_addr = sb + 2 * TILE_A +
                          (uint32_t)((wn * (NT / 2) + (lane >> 4) * 8 + (lane & 7)) * 80 +
                                     ((lane >> 3) & 1) * 16);

#pragma unroll
        for (int ks = 0; ks < 2; ks++) {
            uint32_t ah[2][4], al[2][4];
#pragma unroll
            for (int mb = 0; mb < 2; mb++) {
                uint32_t ao = a_addr + ks * 32 + mb * (16 * 80);
                ldsm4(ah[mb][0], ah[mb][1], ah[mb][2], ah[mb][3], ao);
                if (SPLITS == 3)
                    ldsm4(al[mb][0], al[mb][1], al[mb][2], al[mb][3], ao + TILE_A);
            }
#pragma unroll
            for (int np = 0; np < NP; np++) {
                uint32_t bo = b_addr + ks * 32 + np * (16 * 80);
                uint32_t h0, h1, h2, h3, l0, l1, l2, l3;
                ldsm4(h0, h1, h2, h3, bo);
                if (SPLITS == 3) ldsm4(l0, l1, l2, l3, bo + TILE_W);
#pragma unroll
                for (int mb = 0; mb < 2; mb++) {
                    mma_bf16(acc[mb][2 * np],     ah[mb], h0, h1);
                    mma_bf16(acc[mb][2 * np + 1], ah[mb], h2, h3);
                    if (SPLITS == 3) {
                        mma_bf16(acc[mb][2 * np],     al[mb], h0, h1);
                        mma_bf16(acc[mb][2 * np],     ah[mb], l0, l1);
                        mma_bf16(acc[mb][2 * np + 1], al[mb], h2, h3);
                        mma_bf16(acc[mb][2 * np + 1], ah[mb], l2, l3);
                    }
                }
            }
        }
        __syncthreads();
    }

    int lr = lane >> 2, lc = lane & 3;
#pragma unroll
    for (int mb = 0; mb < 2; mb++) {
#pragma unroll
        for (int nb = 0; nb < 2 * NP; nb++) {
            int n = n0 + wn * (NT / 2) + nb * 8 + lc * 2;
            int m_lo = m0 + wm * 32 + mb * 16 + lr;
            float* a4 = acc[mb][nb];
            if constexpr (MODE == 0) {
                float2 bv = *(const float2*)(bias + n);
                *(float2*)(Cout + (size_t)m_lo * 1024 + n) =
                    make_float2(a4[0] + bv.x, a4[1] + bv.y);
                *(float2*)(Cout + (size_t)(m_lo + 8) * 1024 + n) =
                    make_float2(a4[2] + bv.x, a4[3] + bv.y);
            } else if constexpr (MODE == 1) {
                float2 bv = *(const float2*)(bias + n);
                int which = n >> 10;
                int hh = (n & 1023) >> 6;
                int d = n & 63;
#pragma unroll
                for (int half = 0; half < 2; half++) {
                    int m = m_lo + half * 8;
                    int b_ = m >> 11;
                    int s = m & 2047;
                    float v0 = a4[2 * half] + bv.x;
                    float v1 = a4[2 * half + 1] + bv.y;
                    size_t idx = (((size_t)b_ * HH + hh) * SS + s) * DD + d;
                    if (which == 2) {
                        *(float2*)(g_qkv + 2 * QKPLANE + idx) = make_float2(v0, v1);
                    } else {
                        uint32_t hi;
                        asm("cvt.rn.bf16x2.f32 %0, %1, %2;" : "=r"(hi) : "f"(v1), "f"(v0));
                        uint32_t* ph = which ? (uint32_t*)g_k_hi : (uint32_t*)g_q_hi;
                        ph[idx >> 1] = hi;
                    }
                }
            } else if constexpr (MODE == 2) {
                float* Sp = Cout + (size_t)z * SPLANE;
                *(float2*)(Sp + (size_t)m_lo * SS + n) = make_float2(a4[0], a4[1]);
                *(float2*)(Sp + (size_t)(m_lo + 8) * SS + n) = make_float2(a4[2], a4[3]);
            } else {
                // MODE 3: ctx -> bf16 hi/lo into g_a, layout [b][s][h*64+d]
                int b_ = z >> 4, h_ = z & 15;
                uint32_t* ch = (uint32_t*)g_a_hi;
                uint32_t* cl = (uint32_t*)g_a_lo;
                size_t i0 = ((size_t)(b_ * SS + m_lo) * EE + h_ * DD + n) >> 1;
                size_t i1 = i0 + 4 * EE;
                uint32_t hi, lo;
                split2(a4[0], a4[1], hi, lo);
                ch[i0] = hi; cl[i0] = lo;
                split2(a4[2], a4[3], hi, lo);
                ch[i1] = hi; cl[i1] = lo;
            }
        }
    }
}

// ===========================================================================
extern "C" void kernel_launch(void* const* d_in, const int* in_sizes, int n_in,
                              void* d_out, int out_size) {
    const float* x     = (const float*)d_in[0];
    const float* w_qkv = (const float*)d_in[1];
    const float* b_qkv = (const float*)d_in[2];
    const float* w_out = (const float*)d_in[3];
    const float* b_out = (const float*)d_in[4];
    float* out = (float*)d_out;

    void *p_S, *p_phi, *p_plo, *p_ahi, *p_alo, *p_wqh, *p_wql, *p_woh, *p_wol,
         *p_qhi, *p_khi, *p_vth, *p_vtl;
    cudaGetSymbolAddress(&p_S, g_S);
    cudaGetSymbolAddress(&p_phi, g_p_hi);
    cudaGetSymbolAddress(&p_plo, g_p_lo);
    cudaGetSymbolAddress(&p_ahi, g_a_hi);
    cudaGetSymbolAddress(&p_alo, g_a_lo);
    cudaGetSymbolAddress(&p_wqh, g_wq_hi);
    cudaGetSymbolAddress(&p_wql, g_wq_lo);
    cudaGetSymbolAddress(&p_woh, g_wo_hi);
    cudaGetSymbolAddress(&p_wol, g_wo_lo);
    cudaGetSymbolAddress(&p_qhi, g_q_hi);
    cudaGetSymbolAddress(&p_khi, g_k_hi);
    cudaGetSymbolAddress(&p_vth, g_vt_hi);
    cudaGetSymbolAddress(&p_vtl, g_vt_lo);

    const int SM128 = 2 * (2 * 10240 + 2 * 10240);
    const int SM64  = 2 * (2 * 10240 + 2 * 5120);
    cudaFuncSetAttribute(tgemm<1, 128, 1024, 3>, cudaFuncAttributeMaxDynamicSharedMemorySize, SM128);
    cudaFuncSetAttribute(tgemm<0, 128, 1024, 3>, cudaFuncAttributeMaxDynamicSharedMemorySize, SM128);
    cudaFuncSetAttribute(tgemm<2, 128, 64, 1>,   cudaFuncAttributeMaxDynamicSharedMemorySize, SM128);
    cudaFuncSetAttribute(tgemm<3, 64, 2048, 3>,  cudaFuncAttributeMaxDynamicSharedMemorySize, SM64);

    // 1) split x, w_qkv, w_out
    cvt_split_p<<<4096, 256>>>((const float4*)x, (uint2*)p_ahi, (uint2*)p_alo);
    cvt_split_p<<<3072, 256>>>((const float4*)w_qkv, (uint2*)p_wqh, (uint2*)p_wql);
    cvt_split_p<<<1024, 256>>>((const float4*)w_out, (uint2*)p_woh, (uint2*)p_wol);

    // 2) QKV projection -> Q,K rn-bf16 + V fp32
    tgemm<1, 128, 1024, 3><<<dim3(24, 32, 1), 256, SM128>>>(
        (const __nv_bfloat16*)p_ahi, (const __nv_bfloat16*)p_alo,
        (const __nv_bfloat16*)p_wqh, (const __nv_bfloat16*)p_wql,
        b_qkv, nullptr, 0, 0);

    // 3) transpose+split V
    vt_split<<<4096, 256>>>();

    // 4) scores S = Q K^T (bf16-only, 1 MMA)
    tgemm<2, 128, 64, 1><<<dim3(16, 16, 32), 256, SM128>>>(
        (const __nv_bfloat16*)p_qhi, (const __nv_bfloat16*)p_qhi,
        (const __nv_bfloat16*)p_khi, (const __nv_bfloat16*)p_khi,
        nullptr, (float*)p_S, SS * DD, SS * DD);

    // 5) softmax over heads -> P hi/lo
    softmax_h<<<8192, 256>>>();

    // 6) ctx = P V -> ctx bf16 splits in g_a
    tgemm<3, 64, 2048, 3><<<dim3(1, 16, 32), 256, SM64>>>(
        (const __nv_bfloat16*)p_phi, (const __nv_bfloat16*)p_plo,
        (const __nv_bfloat16*)p_vth, (const __nv_bfloat16*)p_vtl,
        nullptr, nullptr, (int)SPLANE, DD * SS);

    // 7) out-projection
    tgemm<0, 128, 1024, 3><<<dim3(8, 32, 1), 256, SM128>>>(
        (const __nv_bfloat16*)p_ahi, (const __nv_bfloat16*)p_alo,
        (const __nv_bfloat16*)p_woh, (const __nv_bfloat16*)p_wol,
        b_out, out, 0, 0);
}

// round 11
// speedup vs baseline: 2.0153x; 1.7292x over previous
#include <cuda_runtime.h>
#include <cuda_fp16.h>
#include <cstdint>

#define BB 2
#define SS 2048
#define EE 1024
#define HH 16
#define DD 64
#define QKPLANE (BB * HH * SS * DD)
#define SPLANE ((size_t)SS * SS)

__device__ __half g_x16[4096 * 1024];             // x fp16, later reused? (no)
__device__ __half g_wq16[3072 * 1024];
__device__ __half g_wo16[1024 * 1024];
__device__ __half g_q16[QKPLANE];                 // [b][h][s][d]
__device__ __half g_k16[QKPLANE];
__device__ __half g_vt16[QKPLANE];                // [b][h][d][k]
__device__ __half g_S16[(size_t)BB * HH * SS * SS];
__device__ __half g_P16[(size_t)BB * HH * SS * SS];
__device__ __half g_ctx16[BB * SS * EE];          // [b][s][h*64+d]

// ===========================================================================
// helpers
// ===========================================================================
__device__ __forceinline__ uint32_t smem_u32(const void* p) {
    uint32_t a;
    asm("{ .reg .u64 t; cvta.to.shared.u64 t, %1; cvt.u32.u64 %0, t; }"
        : "=r"(a) : "l"(p));
    return a;
}
__device__ __forceinline__ void cp_async16(uint32_t saddr, const void* g) {
    asm volatile("cp.async.cg.shared.global [%0], [%1], 16;\n" :: "r"(saddr), "l"(g));
}
__device__ __forceinline__ void cp_commit() {
    asm volatile("cp.async.commit_group;\n" ::: "memory");
}
__device__ __forceinline__ void ldsm4(uint32_t& r0, uint32_t& r1, uint32_t& r2,
                                      uint32_t& r3, uint32_t a) {
    asm volatile("ldmatrix.sync.aligned.m8n8.x4.shared.b16 {%0,%1,%2,%3}, [%4];"
                 : "=r"(r0), "=r"(r1), "=r"(r2), "=r"(r3) : "r"(a));
}
__device__ __forceinline__ void mma_f16(float* c, const uint32_t* a, uint32_t b0,
                                        uint32_t b1) {
    asm volatile(
        "mma.sync.aligned.m16n8k16.row.col.f32.f16.f16.f32 "
        "{%0,%1,%2,%3},{%4,%5,%6,%7},{%8,%9},{%0,%1,%2,%3};"
        : "+f"(c[0]), "+f"(c[1]), "+f"(c[2]), "+f"(c[3])
        : "r"(a[0]), "r"(a[1]), "r"(a[2]), "r"(a[3]), "r"(b0), "r"(b1));
}
__device__ __forceinline__ uint32_t pack_h2(float a, float b) {
    uint32_t r;
    asm("cvt.rn.f16x2.f32 %0, %1, %2;" : "=r"(r) : "f"(b), "f"(a));
    return r;   // lo = a, hi = b
}

// ===========================================================================
// fp32 -> fp16 convert
// ===========================================================================
__global__ __launch_bounds__(256) void cvt16(const float4* __restrict__ src,
                                             uint2* __restrict__ dst) {
    int i = blockIdx.x * 256 + threadIdx.x;
    float4 v = src[i];
    dst[i] = make_uint2(pack_h2(v.x, v.y), pack_h2(v.z, v.w));
}

// ===========================================================================
// softmax over HEAD axis (fp16 S -> fp16 P)
// ===========================================================================
__global__ __launch_bounds__(256) void softmax16() {
    int idx = blockIdx.x * 256 + threadIdx.x;   // 2*2048*512
    int k4 = idx & 511;
    int q = (idx >> 9) & 2047;
    int b = idx >> 20;
    const uint2* Sp = (const uint2*)g_S16;
    uint2* Pp = (uint2*)g_P16;
    size_t base = ((size_t)(b * HH) * SS + q) * 512 + k4;
    size_t hstep = (size_t)SS * 512;

    float4 e[16];
    float4 ds = make_float4(0.f, 0.f, 0.f, 0.f);
#pragma unroll
    for (int h = 0; h < 16; h++) {
        uint2 u = Sp[base + (size_t)h * hstep];
        float2 f0 = __half22float2(*(const __half2*)&u.x);
        float2 f1 = __half22float2(*(const __half2*)&u.y);
        e[h].x = __expf(f0.x * 0.03125f);
        e[h].y = __expf(f0.y * 0.03125f);
        e[h].z = __expf(f1.x * 0.03125f);
        e[h].w = __expf(f1.y * 0.03125f);
        ds.x += e[h].x; ds.y += e[h].y; ds.z += e[h].z; ds.w += e[h].w;
    }
    float4 r;
    r.x = __fdividef(1.f, ds.x);
    r.y = __fdividef(1.f, ds.y);
    r.z = __fdividef(1.f, ds.z);
    r.w = __fdividef(1.f, ds.w);
#pragma unroll
    for (int h = 0; h < 16; h++) {
        uint2 o;
        o.x = pack_h2(e[h].x * r.x, e[h].y * r.y);
        o.y = pack_h2(e[h].z * r.z, e[h].w * r.w);
        Pp[base + (size_t)h * hstep] = o;
    }
}

// ===========================================================================
// fp16 HMMA NT GEMM (single-MMA): C = A[M,K] @ W[N,K]^T
// MODE 0: out-proj (bias, fp32 out N=1024)
// MODE 1: QKV (bias; Q,K fp16 [b][h][s][d]; V fp16 TRANSPOSED [b][h][d][k])
// MODE 2: scores (z=(b,h), K=64, fp16 S out)
// MODE 3: PV (z=(b,h), NT=64; fp16 ctx out [b][s][e])
// ===========================================================================
template <int MODE, int NT, int K>
__global__ __launch_bounds__(256, 2) void tgemm16(
    const __half* __restrict__ A0, const __half* __restrict__ W0,
    const float* __restrict__ bias, float* __restrict__ Cout,
    int strideA, int strideW) {
    extern __shared__ char dsm[];
    uint32_t sbase = smem_u32(dsm);
    constexpr int TILE_A = 10240;          // 128 rows * 80B (64B data + 16 pad)
    constexpr int TILE_W = NT * 80;
    constexpr int BUF = TILE_A + TILE_W;
    constexpr int NP = NT / 32;

    int z = blockIdx.z;
    const __half* A = A0 + (size_t)z * strideA;
    const __half* W = W0 + (size_t)z * strideW;

    int tid = threadIdx.x, lane = tid & 31, wid = tid >> 5;
    int wm = wid & 3, wn = wid >> 2;
    int m0 = blockIdx.y * 128, n0 = blockIdx.x * NT;

    float acc[2][2 * NP][4];
#pragma unroll
    for (int i = 0; i < 2; i++)
#pragma unroll
        for (int j = 0; j < 2 * NP; j++)
#pragma unroll
            for (int q = 0; q < 4; q++) acc[i][j][q] = 0.f;

    const int NC = K / 32;
    const int lrow = tid >> 2;
    const int seg = tid & 3;

    auto issue = [&](int c) {
        uint32_t sb = sbase + (c & 1) * BUF;
        int gcol = c * 32 + seg * 8;
#pragma unroll
        for (int rr = 0; rr < 2; rr++) {
            int row = lrow + rr * 64;
            uint32_t soff = (uint32_t)(row * 80 + seg * 16);
            cp_async16(sb + soff, A + (size_t)(m0 + row) * K + gcol);
        }
#pragma unroll
        for (int rr = 0; rr < NT / 64; rr++) {
            int row = lrow + rr * 64;
            uint32_t soff = (uint32_t)(row * 80 + seg * 16);
            cp_async16(sb + TILE_A + soff, W + (size_t)(n0 + row) * K + gcol);
        }
        cp_commit();
    };

    issue(0);

    for (int c = 0; c < NC; c++) {
        if (c + 1 < NC) {
            issue(c + 1);
            asm volatile("cp.async.wait_group 1;\n" ::: "memory");
        } else {
            asm volatile("cp.async.wait_group 0;\n" ::: "memory");
        }
        __syncthreads();

        uint32_t sb = sbase + (c & 1) * BUF;
        uint32_t a_addr = sb + (uint32_t)((wm * 32 + (lane & 15)) * 80 + (lane >> 4) * 16);
        uint32_t b_addr = sb + TILE_A +
                          (uint32_t)((wn * (NT / 2) + (lane >> 4) * 8 + (lane & 7)) * 80 +
                                     ((lane >> 3) & 1) * 16);

#pragma unroll
        for (int ks = 0; ks < 2; ks++) {
            uint32_t ah[2][4];
#pragma unroll
            for (int mb = 0; mb < 2; mb++) {
                uint32_t ao = a_addr + ks * 32 + mb * (16 * 80);
                ldsm4(ah[mb][0], ah[mb][1], ah[mb][2], ah[mb][3], ao);
            }
#pragma unroll
            for (int np = 0; np < NP; np++) {
                uint32_t bo = b_addr + ks * 32 + np * (16 * 80);
                uint32_t h0, h1, h2, h3;
                ldsm4(h0, h1, h2, h3, bo);
#pragma unroll
                for (int mb = 0; mb < 2; mb++) {
                    mma_f16(acc[mb][2 * np],     ah[mb], h0, h1);
                    mma_f16(acc[mb][2 * np + 1], ah[mb], h2, h3);
                }
            }
        }
        __syncthreads();
    }

    int lr = lane >> 2, lc = lane & 3;
#pragma unroll
    for (int mb = 0; mb < 2; mb++) {
#pragma unroll
        for (int nb = 0; nb < 2 * NP; nb++) {
            int n = n0 + wn * (NT / 2) + nb * 8 + lc * 2;
            int m_lo = m0 + wm * 32 + mb * 16 + lr;
            float* a4 = acc[mb][nb];
            if constexpr (MODE == 0) {
                float2 bv = *(const float2*)(bias + n);
                *(float2*)(Cout + (size_t)m_lo * 1024 + n) =
                    make_float2(a4[0] + bv.x, a4[1] + bv.y);
                *(float2*)(Cout + (size_t)(m_lo + 8) * 1024 + n) =
                    make_float2(a4[2] + bv.x, a4[3] + bv.y);
            } else if constexpr (MODE == 1) {
                float2 bv = *(const float2*)(bias + n);
                int which = n >> 10;
                int hh = (n & 1023) >> 6;
                int d = n & 63;
#pragma unroll
                for (int half_ = 0; half_ < 2; half_++) {
                    int m = m_lo + half_ * 8;
                    int b_ = m >> 11;
                    int s = m & 2047;
                    float v0 = a4[2 * half_] + bv.x;
                    float v1 = a4[2 * half_ + 1] + bv.y;
                    if (which == 2) {
                        // V transposed: [b][h][d][k]
                        size_t tb = ((size_t)(b_ * HH + hh) * DD + d) * SS + s;
                        g_vt16[tb] = __float2half_rn(v0);
                        g_vt16[tb + SS] = __float2half_rn(v1);
                    } else {
                        size_t idx = (((size_t)b_ * HH + hh) * SS + s) * DD + d;
                        uint32_t* ph = which ? (uint32_t*)g_k16 : (uint32_t*)g_q16;
                        ph[idx >> 1] = pack_h2(v0, v1);
                    }
                }
            } else if constexpr (MODE == 2) {
                uint32_t* Sp = (uint32_t*)(g_S16 + (size_t)z * SPLANE);
                Sp[((size_t)m_lo * SS + n) >> 1] = pack_h2(a4[0], a4[1]);
                Sp[((size_t)(m_lo + 8) * SS + n) >> 1] = pack_h2(a4[2], a4[3]);
            } else {
                // MODE 3: ctx fp16 into [b][s][h*64+d]
                int b_ = z >> 4, h_ = z & 15;
                uint32_t* ch = (uint32_t*)g_ctx16;
                size_t i0 = ((size_t)(b_ * SS + m_lo) * EE + h_ * DD + n) >> 1;
                ch[i0] = pack_h2(a4[0], a4[1]);
                ch[i0 + 4 * EE] = pack_h2(a4[2], a4[3]);
            }
        }
    }
}

// ===========================================================================
extern "C" void kernel_launch(void* const* d_in, const int* in_sizes, int n_in,
                              void* d_out, int out_size) {
    const float* x     = (const float*)d_in[0];
    const float* w_qkv = (const float*)d_in[1];
    const float* b_qkv = (const float*)d_in[2];
    const float* w_out = (const float*)d_in[3];
    const float* b_out = (const float*)d_in[4];
    float* out = (float*)d_out;

    void *p_x, *p_wq, *p_wo, *p_q, *p_k, *p_vt, *p_P, *p_ctx;
    cudaGetSymbolAddress(&p_x, g_x16);
    cudaGetSymbolAddress(&p_wq, g_wq16);
    cudaGetSymbolAddress(&p_wo, g_wo16);
    cudaGetSymbolAddress(&p_q, g_q16);
    cudaGetSymbolAddress(&p_k, g_k16);
    cudaGetSymbolAddress(&p_vt, g_vt16);
    cudaGetSymbolAddress(&p_P, g_P16);
    cudaGetSymbolAddress(&p_ctx, g_ctx16);

    const int SM128 = 2 * (10240 + 10240);   // 40960
    const int SM64  = 2 * (10240 + 5120);    // 30720
    cudaFuncSetAttribute(tgemm16<1, 128, 1024>, cudaFuncAttributeMaxDynamicSharedMemorySize, SM128);
    cudaFuncSetAttribute(tgemm16<0, 128, 1024>, cudaFuncAttributeMaxDynamicSharedMemorySize, SM128);
    cudaFuncSetAttribute(tgemm16<2, 128, 64>,   cudaFuncAttributeMaxDynamicSharedMemorySize, SM128);
    cudaFuncSetAttribute(tgemm16<3, 64, 2048>,  cudaFuncAttributeMaxDynamicSharedMemorySize, SM64);

    // 1) fp32 -> fp16 converts
    cvt16<<<4096, 256>>>((const float4*)x, (uint2*)p_x);
    cvt16<<<3072, 256>>>((const float4*)w_qkv, (uint2*)p_wq);
    cvt16<<<1024, 256>>>((const float4*)w_out, (uint2*)p_wo);

    // 2) QKV projection -> Q,K fp16 + V fp16 transposed
    tgemm16<1, 128, 1024><<<dim3(24, 32, 1), 256, SM128>>>(
        (const __half*)p_x, (const __half*)p_wq, b_qkv, nullptr, 0, 0);

    // 3) scores S = Q K^T -> fp16
    tgemm16<2, 128, 64><<<dim3(16, 16, 32), 256, SM128>>>(
        (const __half*)p_q, (const __half*)p_k, nullptr, nullptr,
        SS * DD, SS * DD);

    // 4) softmax over heads -> P fp16
    softmax16<<<8192, 256>>>();

    // 5) ctx = P V -> fp16 [b][s][e]
    tgemm16<3, 64, 2048><<<dim3(1, 16, 32), 256, SM64>>>(
        (const __half*)p_P, (const __half*)p_vt, nullptr, nullptr,
        (int)SPLANE, DD * SS);

    // 6) out-projection -> fp32 out
    tgemm16<0, 128, 1024><<<dim3(8, 32, 1), 256, SM128>>>(
        (const __half*)p_ctx, (const __half*)p_wo, b_out, out, 0, 0);
}

// round 12
// speedup vs baseline: 2.1883x; 1.0859x over previous
#include <cuda_runtime.h>
#include <cuda_fp16.h>
#include <cstdint>

#define BB 2
#define SS 2048
#define EE 1024
#define HH 16
#define DD 64
#define QKPLANE (BB * HH * SS * DD)
#define SPLANE ((size_t)SS * SS)

__device__ __half g_x16[4096 * 1024];
__device__ __half g_wq16[3072 * 1024];
__device__ __half g_wo16[1024 * 1024];
__device__ __half g_q16[QKPLANE];                 // [b][h][s][d]
__device__ __half g_k16[QKPLANE];
__device__ __half g_vt16[QKPLANE];                // [b][h][d][k]
__device__ __half g_S16[(size_t)BB * HH * SS * SS];
__device__ __half g_P16[(size_t)BB * HH * SS * SS];
__device__ __half g_ctx16[BB * SS * EE];          // [b][s][h*64+d]

// ===========================================================================
// helpers
// ===========================================================================
__device__ __forceinline__ uint32_t smem_u32(const void* p) {
    uint32_t a;
    asm("{ .reg .u64 t; cvta.to.shared.u64 t, %1; cvt.u32.u64 %0, t; }"
        : "=r"(a) : "l"(p));
    return a;
}
__device__ __forceinline__ void cp_async16(uint32_t saddr, const void* g) {
    asm volatile("cp.async.cg.shared.global [%0], [%1], 16;\n" :: "r"(saddr), "l"(g));
}
__device__ __forceinline__ void cp_commit() {
    asm volatile("cp.async.commit_group;\n" ::: "memory");
}
__device__ __forceinline__ void ldsm4(uint32_t& r0, uint32_t& r1, uint32_t& r2,
                                      uint32_t& r3, uint32_t a) {
    asm volatile("ldmatrix.sync.aligned.m8n8.x4.shared.b16 {%0,%1,%2,%3}, [%4];"
                 : "=r"(r0), "=r"(r1), "=r"(r2), "=r"(r3) : "r"(a));
}
__device__ __forceinline__ void mma_f16(float* c, const uint32_t* a, uint32_t b0,
                                        uint32_t b1) {
    asm volatile(
        "mma.sync.aligned.m16n8k16.row.col.f32.f16.f16.f32 "
        "{%0,%1,%2,%3},{%4,%5,%6,%7},{%8,%9},{%0,%1,%2,%3};"
        : "+f"(c[0]), "+f"(c[1]), "+f"(c[2]), "+f"(c[3])
        : "r"(a[0]), "r"(a[1]), "r"(a[2]), "r"(a[3]), "r"(b0), "r"(b1));
}
__device__ __forceinline__ uint32_t pack_h2(float a, float b) {
    uint32_t r;
    asm("cvt.rn.f16x2.f32 %0, %1, %2;" : "=r"(r) : "f"(b), "f"(a));
    return r;
}

// ===========================================================================
// fp32 -> fp16 convert
// ===========================================================================
__global__ __launch_bounds__(256) void cvt16(const float4* __restrict__ src,
                                             uint2* __restrict__ dst) {
    int i = blockIdx.x * 256 + threadIdx.x;
    float4 v = src[i];
    dst[i] = make_uint2(pack_h2(v.x, v.y), pack_h2(v.z, v.w));
}

// ===========================================================================
// softmax over HEAD axis (fp16 S -> fp16 P)
// ===========================================================================
__global__ __launch_bounds__(256) void softmax16() {
    int idx = blockIdx.x * 256 + threadIdx.x;
    int k4 = idx & 511;
    int q = (idx >> 9) & 2047;
    int b = idx >> 20;
    const uint2* Sp = (const uint2*)g_S16;
    uint2* Pp = (uint2*)g_P16;
    size_t base = ((size_t)(b * HH) * SS + q) * 512 + k4;
    size_t hstep = (size_t)SS * 512;

    float4 e[16];
    float4 ds = make_float4(0.f, 0.f, 0.f, 0.f);
#pragma unroll
    for (int h = 0; h < 16; h++) {
        uint2 u = Sp[base + (size_t)h * hstep];
        float2 f0 = __half22float2(*(const __half2*)&u.x);
        float2 f1 = __half22float2(*(const __half2*)&u.y);
        e[h].x = __expf(f0.x * 0.03125f);
        e[h].y = __expf(f0.y * 0.03125f);
        e[h].z = __expf(f1.x * 0.03125f);
        e[h].w = __expf(f1.y * 0.03125f);
        ds.x += e[h].x; ds.y += e[h].y; ds.z += e[h].z; ds.w += e[h].w;
    }
    float4 r;
    r.x = __fdividef(1.f, ds.x);
    r.y = __fdividef(1.f, ds.y);
    r.z = __fdividef(1.f, ds.z);
    r.w = __fdividef(1.f, ds.w);
#pragma unroll
    for (int h = 0; h < 16; h++) {
        uint2 o;
        o.x = pack_h2(e[h].x * r.x, e[h].y * r.y);
        o.y = pack_h2(e[h].z * r.z, e[h].w * r.w);
        Pp[base + (size_t)h * hstep] = o;
    }
}

// ===========================================================================
// fp16 HMMA NT GEMM, templated K-chunk depth KB.
// MODE 0: out-proj (bias, fp32 out N=1024)
// MODE 1: QKV (bias; Q,K fp16 [b][h][s][d]; V fp16 transposed [b][h][d][k])
// MODE 2: scores (z=(b,h), fp16 S out)
// MODE 3: PV (z=(b,h), NT=64; fp16 ctx out [b][s][e])
// ===========================================================================
template <int MODE, int NT, int K, int KB>
__global__ __launch_bounds__(256, 2) void tgemm16(
    const __half* __restrict__ A0, const __half* __restrict__ W0,
    const float* __restrict__ bias, float* __restrict__ Cout,
    int strideA, int strideW) {
    extern __shared__ char dsm[];
    uint32_t sbase = smem_u32(dsm);
    constexpr int PITCH = KB * 2 + 16;
    constexpr int TILE_A = 128 * PITCH;
    constexpr int TILE_W = NT * PITCH;
    constexpr int BUF = TILE_A + TILE_W;
    constexpr int NP = NT / 32;
    constexpr int SEG = KB / 8;          // 16B segments per row
    constexpr int NKS = KB / 16;         // k-steps per chunk

    int z = blockIdx.z;
    const __half* A = A0 + (size_t)z * strideA;
    const __half* W = W0 + (size_t)z * strideW;

    int tid = threadIdx.x, lane = tid & 31, wid = tid >> 5;
    int wm = wid & 3, wn = wid >> 2;
    int m0 = blockIdx.y * 128, n0 = blockIdx.x * NT;

    float acc[2][2 * NP][4];
#pragma unroll
    for (int i = 0; i < 2; i++)
#pragma unroll
        for (int j = 0; j < 2 * NP; j++)
#pragma unroll
            for (int q = 0; q < 4; q++) acc[i][j][q] = 0.f;

    const int NC = K / KB;

    auto issue = [&](int c) {
        uint32_t sb = sbase + (c & 1) * BUF;
        int gc = c * KB;
#pragma unroll
        for (int it = 0; it < 128 * SEG / 256; it++) {
            int idx = tid + it * 256;
            int row = idx / SEG, seg = idx % SEG;
            cp_async16(sb + (uint32_t)(row * PITCH + seg * 16),
                       A + (size_t)(m0 + row) * K + gc + seg * 8);
        }
#pragma unroll
        for (int it = 0; it < NT * SEG / 256; it++) {
            int idx = tid + it * 256;
            int row = idx / SEG, seg = idx % SEG;
            cp_async16(sb + (uint32_t)(TILE_A + row * PITCH + seg * 16),
                       W + (size_t)(n0 + row) * K + gc + seg * 8);
        }
        cp_commit();
    };

    issue(0);

    for (int c = 0; c < NC; c++) {
        if (c + 1 < NC) {
            issue(c + 1);
            asm volatile("cp.async.wait_group 1;\n" ::: "memory");
        } else {
            asm volatile("cp.async.wait_group 0;\n" ::: "memory");
        }
        __syncthreads();

        uint32_t sb = sbase + (c & 1) * BUF;
        uint32_t a_addr = sb + (uint32_t)((wm * 32 + (lane & 15)) * PITCH + (lane >> 4) * 16);
        uint32_t b_addr = sb + TILE_A +
                          (uint32_t)((wn * (NT / 2) + (lane >> 4) * 8 + (lane & 7)) * PITCH +
                                     ((lane >> 3) & 1) * 16);

#pragma unroll
        for (int ks = 0; ks < NKS; ks++) {
            uint32_t ah[2][4];
#pragma unroll
            for (int mb = 0; mb < 2; mb++) {
                uint32_t ao = a_addr + ks * 32 + mb * (16 * PITCH);
                ldsm4(ah[mb][0], ah[mb][1], ah[mb][2], ah[mb][3], ao);
            }
#pragma unroll
            for (int np = 0; np < NP; np++) {
                uint32_t bo = b_addr + ks * 32 + np * (16 * PITCH);
                uint32_t h0, h1, h2, h3;
                ldsm4(h0, h1, h2, h3, bo);
#pragma unroll
                for (int mb = 0; mb < 2; mb++) {
                    mma_f16(acc[mb][2 * np],     ah[mb], h0, h1);
                    mma_f16(acc[mb][2 * np + 1], ah[mb], h2, h3);
                }
            }
        }
        __syncthreads();
    }

    int lr = lane >> 2, lc = lane & 3;
#pragma unroll
    for (int mb = 0; mb < 2; mb++) {
#pragma unroll
        for (int nb = 0; nb < 2 * NP; nb++) {
            int n = n0 + wn * (NT / 2) + nb * 8 + lc * 2;
            int m_lo = m0 + wm * 32 + mb * 16 + lr;
            float* a4 = acc[mb][nb];
            if constexpr (MODE == 0) {
                float2 bv = *(const float2*)(bias + n);
                *(float2*)(Cout + (size_t)m_lo * 1024 + n) =
                    make_float2(a4[0] + bv.x, a4[1] + bv.y);
                *(float2*)(Cout + (size_t)(m_lo + 8) * 1024 + n) =
                    make_float2(a4[2] + bv.x, a4[3] + bv.y);
            } else if constexpr (MODE == 1) {
                float2 bv = *(const float2*)(bias + n);
                int which = n >> 10;
                int hh = (n & 1023) >> 6;
                int d = n & 63;
#pragma unroll
                for (int half_ = 0; half_ < 2; half_++) {
                    int m = m_lo + half_ * 8;
                    int b_ = m >> 11;
                    int s = m & 2047;
                    float v0 = a4[2 * half_] + bv.x;
                    float v1 = a4[2 * half_ + 1] + bv.y;
                    if (which == 2) {
                        size_t tb = ((size_t)(b_ * HH + hh) * DD + d) * SS + s;
                        g_vt16[tb] = __float2half_rn(v0);
                        g_vt16[tb + SS] = __float2half_rn(v1);
                    } else {
                        size_t idx = (((size_t)b_ * HH + hh) * SS + s) * DD + d;
                        uint32_t* ph = which ? (uint32_t*)g_k16 : (uint32_t*)g_q16;
                        ph[idx >> 1] = pack_h2(v0, v1);
                    }
                }
            } else if constexpr (MODE == 2) {
                uint32_t* Sp = (uint32_t*)(g_S16 + (size_t)z * SPLANE);
                Sp[((size_t)m_lo * SS + n) >> 1] = pack_h2(a4[0], a4[1]);
                Sp[((size_t)(m_lo + 8) * SS + n) >> 1] = pack_h2(a4[2], a4[3]);
            } else {
                int b_ = z >> 4, h_ = z & 15;
                uint32_t* ch = (uint32_t*)g_ctx16;
                size_t i0 = ((size_t)(b_ * SS + m_lo) * EE + h_ * DD + n) >> 1;
                ch[i0] = pack_h2(a4[0], a4[1]);
                ch[i0 + 4 * EE] = pack_h2(a4[2], a4[3]);
            }
        }
    }
}

// ===========================================================================
extern "C" void kernel_launch(void* const* d_in, const int* in_sizes, int n_in,
                              void* d_out, int out_size) {
    const float* x     = (const float*)d_in[0];
    const float* w_qkv = (const float*)d_in[1];
    const float* b_qkv = (const float*)d_in[2];
    const float* w_out = (const float*)d_in[3];
    const float* b_out = (const float*)d_in[4];
    float* out = (float*)d_out;

    void *p_x, *p_wq, *p_wo, *p_q, *p_k, *p_vt, *p_P, *p_ctx;
    cudaGetSymbolAddress(&p_x, g_x16);
    cudaGetSymbolAddress(&p_wq, g_wq16);
    cudaGetSymbolAddress(&p_wo, g_wo16);
    cudaGetSymbolAddress(&p_q, g_q16);
    cudaGetSymbolAddress(&p_k, g_k16);
    cudaGetSymbolAddress(&p_vt, g_vt16);
    cudaGetSymbolAddress(&p_P, g_P16);
    cudaGetSymbolAddress(&p_ctx, g_ctx16);

    const int SM_QKV = 2 * (128 * 144 + 128 * 144);   // 73728 (KB=64, NT=128)
    const int SM_SC  = 2 * (128 * 80 + 128 * 80);     // 40960 (KB=32, NT=128)
    const int SM_PV  = 2 * (128 * 144 + 64 * 144);    // 55296 (KB=64, NT=64)
    cudaFuncSetAttribute(tgemm16<1, 128, 1024, 64>, cudaFuncAttributeMaxDynamicSharedMemorySize, SM_QKV);
    cudaFuncSetAttribute(tgemm16<0, 128, 1024, 64>, cudaFuncAttributeMaxDynamicSharedMemorySize, SM_QKV);
    cudaFuncSetAttribute(tgemm16<2, 128, 64, 32>,   cudaFuncAttributeMaxDynamicSharedMemorySize, SM_SC);
    cudaFuncSetAttribute(tgemm16<3, 64, 2048, 64>,  cudaFuncAttributeMaxDynamicSharedMemorySize, SM_PV);

    // 1) fp32 -> fp16 converts
    cvt16<<<4096, 256>>>((const float4*)x, (uint2*)p_x);
    cvt16<<<3072, 256>>>((const float4*)w_qkv, (uint2*)p_wq);
    cvt16<<<1024, 256>>>((const float4*)w_out, (uint2*)p_wo);

    // 2) QKV projection -> Q,K fp16 + V fp16 transposed
    tgemm16<1, 128, 1024, 64><<<dim3(24, 32, 1), 256, SM_QKV>>>(
        (const __half*)p_x, (const __half*)p_wq, b_qkv, nullptr, 0, 0);

    // 3) scores S = Q K^T -> fp16
    tgemm16<2, 128, 64, 32><<<dim3(16, 16, 32), 256, SM_SC>>>(
        (const __half*)p_q, (const __half*)p_k, nullptr, nullptr,
        SS * DD, SS * DD);

    // 4) softmax over heads -> P fp16
    softmax16<<<8192, 256>>>();

    // 5) ctx = P V -> fp16 [b][s][e]
    tgemm16<3, 64, 2048, 64><<<dim3(1, 16, 32), 256, SM_PV>>>(
        (const __half*)p_P, (const __half*)p_vt, nullptr, nullptr,
        (int)SPLANE, DD * SS);

    // 6) out-projection -> fp32 out
    tgemm16<0, 128, 1024, 64><<<dim3(8, 32, 1), 256, SM_QKV>>>(
        (const __half*)p_ctx, (const __half*)p_wo, b_out, out, 0, 0);
}